// round 1
// baseline (speedup 1.0000x reference)
#include <cuda_runtime.h>

// SSIM loss, fused single pass.
// pred/target: [16,3,512,512] fp32 -> 48 planes of 512x512.
// Grid: 48 planes * 16 column-tiles = 768 CTAs, 256 threads (8 warps).
// Each warp: 32-column strip (one column per lane), 64-row chunk, streaming
// rows with horizontal conv in smem/registers and vertical conv via
// scatter-accumulate into an 11-deep register ring (no smem for vertical).

static __device__ double g_accum;

__global__ void ssim_init_kernel() { g_accum = 0.0; }

__global__ void ssim_final_kernel(float* __restrict__ out) {
    // mean over 16*3*512*512 = 12,582,912 pixels; loss = 1 - mean(ssim)
    out[0] = (float)(1.0 - g_accum * (1.0 / 12582912.0));
}

__global__ __launch_bounds__(256) void ssim_main_kernel(
    const float* __restrict__ pred, const float* __restrict__ target)
{
    // Gaussian(sigma=1.5), window 11, normalized (matches reference to ~4e-7).
    constexpr float W[11] = {
        0.00102838f, 0.00759876f, 0.03600077f, 0.10936070f, 0.21300553f,
        0.26601212f,
        0.21300553f, 0.10936070f, 0.03600077f, 0.00759876f, 0.00102838f
    };
    constexpr float C1 = 0.0001f;   // 0.01^2
    constexpr float C2 = 0.0009f;   // 0.03^2

    const int lane  = threadIdx.x & 31;
    const int warp  = threadIdx.x >> 5;
    const int plane = blockIdx.x >> 4;         // 0..47
    const int x0    = (blockIdx.x & 15) << 5;  // column tile * 32

    const float* __restrict__ P = pred   + (size_t)plane * (512 * 512);
    const float* __restrict__ T = target + (size_t)plane * (512 * 512);

    const int y0 = warp << 6;   // this warp's first output row (64 rows/warp)

    // Per-warp double-buffered row stage: 42 columns (+pad) for p and t.
    __shared__ float pb[8][2][48];
    __shared__ float tb[8][2][48];

    // Vertical scatter ring: 5 fields x 11 pending output rows.
    float acc[5][11];
#pragma unroll
    for (int f = 0; f < 5; ++f)
#pragma unroll
        for (int s = 0; s < 11; ++s) acc[f][s] = 0.0f;

    float lsum = 0.0f;

    // j = input-row index relative to (y0 - 5); rows j in [0,74).
    // Outer loop strides 11 so ring slots resolve to compile-time constants.
    for (int jb = 0; jb < 77; jb += 11) {
#pragma unroll
        for (int u = 0; u < 11; ++u) {
            const int j = jb + u;
            if (j < 74) {
                const int yy = y0 - 5 + j;    // global input row
                if (yy >= 0 && yy < 512) {
                    const int buf = j & 1;
                    const float* __restrict__ Prow = P + yy * 512;
                    const float* __restrict__ Trow = T + yy * 512;
                    // Stage 42 columns [x0-5, x0+37), zero-padded at edges.
                    {
                        const int c0 = x0 - 5 + lane;
                        const bool v0 = (c0 >= 0) && (c0 < 512);
                        pb[warp][buf][lane] = v0 ? Prow[c0] : 0.0f;
                        tb[warp][buf][lane] = v0 ? Trow[c0] : 0.0f;
                        if (lane < 10) {
                            const int c1 = x0 + 27 + lane;
                            const bool v1 = (c1 < 512);
                            pb[warp][buf][32 + lane] = v1 ? Prow[c1] : 0.0f;
                            tb[warp][buf][32 + lane] = v1 ? Trow[c1] : 0.0f;
                        }
                    }
                    __syncwarp();

                    // Horizontal pass at this lane's column.
                    float hp = 0.0f, ht = 0.0f, hpp = 0.0f, htt = 0.0f, hpt = 0.0f;
#pragma unroll
                    for (int d = 0; d < 11; ++d) {
                        const float pd = pb[warp][buf][lane + d];
                        const float td = tb[warp][buf][lane + d];
                        hp  = fmaf(pd, W[d], hp);       // imm-FMA
                        ht  = fmaf(td, W[d], ht);       // imm-FMA
                        const float wp = pd * W[d];     // imm-MUL
                        const float wt = td * W[d];     // imm-MUL
                        hpp = fmaf(wp, pd, hpp);
                        htt = fmaf(wt, td, htt);
                        hpt = fmaf(wp, td, hpt);
                    }

                    // Vertical scatter: row j feeds output rel-rows r = j-k,
                    // tap weight W[k]. Ring slot (r mod 11) = (u-k) mod 11.
#pragma unroll
                    for (int k = 0; k < 11; ++k) {
                        if (k <= j && (j - k) < 64) {
                            const int s = (u - k + 11) % 11;   // compile-time
                            acc[0][s] = fmaf(hp,  W[k], acc[0][s]);
                            acc[1][s] = fmaf(ht,  W[k], acc[1][s]);
                            acc[2][s] = fmaf(hpp, W[k], acc[2][s]);
                            acc[3][s] = fmaf(htt, W[k], acc[3][s]);
                            acc[4][s] = fmaf(hpt, W[k], acc[4][s]);
                        }
                    }
                }

                // Output rel-row r = j-10 completes after this input row.
                if (j >= 10) {
                    const int s = (u + 1) % 11;   // (j-10) mod 11, compile-time
                    const float mu1 = acc[0][s], mu2 = acc[1][s];
                    const float epp = acc[2][s], ett = acc[3][s], ept = acc[4][s];
                    const float mu1sq = mu1 * mu1;
                    const float mu2sq = mu2 * mu2;
                    const float mu12  = mu1 * mu2;
                    const float s1  = epp - mu1sq;
                    const float s2  = ett - mu2sq;
                    const float s12 = ept - mu12;
                    const float num = (2.0f * mu12 + C1) * (2.0f * s12 + C2);
                    const float den = (mu1sq + mu2sq + C1) * (s1 + s2 + C2);
                    lsum += __fdividef(num, den);
#pragma unroll
                    for (int f = 0; f < 5; ++f) acc[f][s] = 0.0f;
                }
            }
        }
    }

    // Warp-level reduction, then one double atomic per warp.
#pragma unroll
    for (int off = 16; off > 0; off >>= 1)
        lsum += __shfl_xor_sync(0xffffffffu, lsum, off);
    if (lane == 0) atomicAdd(&g_accum, (double)lsum);
}

extern "C" void kernel_launch(void* const* d_in, const int* in_sizes, int n_in,
                              void* d_out, int out_size) {
    const float* pred   = (const float*)d_in[0];
    const float* target = (const float*)d_in[1];
    float* out = (float*)d_out;
    (void)in_sizes; (void)n_in; (void)out_size;

    ssim_init_kernel<<<1, 1>>>();
    ssim_main_kernel<<<768, 256>>>(pred, target);
    ssim_final_kernel<<<1, 1>>>(out);
}

// round 2
// speedup vs baseline: 1.6440x; 1.6440x over previous
#include <cuda_runtime.h>

// SSIM loss, fused single pass, f32x2 packed math.
// pred/target: [16,3,512,512] fp32 -> 48 planes of 512x512.
// Grid: 48 planes * 16 column-tiles = 768 CTAs, 128 threads (4 warps).
// Each warp: 32-column strip (one column/lane), 128 output rows, streaming
// input rows. Fields are packed pairs via a=p+t, b=p-t:
//   accm = (conv(a), conv(b)), accs = (conv(a^2), conv(b^2))
// Horizontal conv in registers from a per-warp smem row stage (LDS.64),
// vertical conv via scatter-accumulate into an 11-deep packed register ring.

static __device__ double g_partials[768];

__device__ __forceinline__ unsigned long long pk2(float lo, float hi) {
    unsigned long long r;
    asm("mov.b64 %0, {%1, %2};" : "=l"(r) : "f"(lo), "f"(hi));
    return r;
}
__device__ __forceinline__ void up2(unsigned long long v, float& lo, float& hi) {
    asm("mov.b64 {%0, %1}, %2;" : "=f"(lo), "=f"(hi) : "l"(v));
}
__device__ __forceinline__ unsigned long long ffma2(unsigned long long a,
                                                    unsigned long long b,
                                                    unsigned long long c) {
    unsigned long long d;
    asm("fma.rn.f32x2 %0, %1, %2, %3;" : "=l"(d) : "l"(a), "l"(b), "l"(c));
    return d;
}
__device__ __forceinline__ unsigned long long fmul2(unsigned long long a,
                                                    unsigned long long b) {
    unsigned long long d;
    asm("mul.rn.f32x2 %0, %1, %2;" : "=l"(d) : "l"(a), "l"(b));
    return d;
}

#define STAGE(BUF, YY) do {                                                  \
    const float* __restrict__ Prow = P + (YY) * 512;                         \
    const float* __restrict__ Trow = T + (YY) * 512;                         \
    float p0 = 0.0f, t0 = 0.0f;                                              \
    if (c0 >= 0) { p0 = Prow[c0]; t0 = Trow[c0]; }                           \
    abw[(BUF) * 48 + lane] = pk2(p0 + t0, p0 - t0);                          \
    if (lane < 10) {                                                         \
        float p1 = 0.0f, t1 = 0.0f;                                          \
        if (c1 < 512) { p1 = Prow[c1]; t1 = Trow[c1]; }                      \
        abw[(BUF) * 48 + 32 + lane] = pk2(p1 + t1, p1 - t1);                 \
    }                                                                        \
    __syncwarp();                                                            \
} while (0)

#define HPASS(BUF) do {                                                      \
    const unsigned long long* __restrict__ rp = abw + (BUF) * 48 + lane;     \
    hm = 0ull; hs = 0ull;                                                    \
    _Pragma("unroll")                                                        \
    for (int d = 0; d < 11; ++d) {                                           \
        const unsigned long long v = rp[d];                                  \
        hm = ffma2(v, Wp[d], hm);                                            \
        hs = ffma2(fmul2(v, Wp[d]), v, hs);                                  \
    }                                                                        \
} while (0)

// UM = j mod 11 (compile-time); KMAX = 10 steady, = j in prologue.
#define VPASS(UM, KMAX) do {                                                 \
    _Pragma("unroll")                                                        \
    for (int k = 0; k <= (KMAX); ++k) {                                      \
        const int s = ((UM) - k + 22) % 11;                                  \
        accm[s] = ffma2(hm, Wp[k], accm[s]);                                 \
        accs[s] = ffma2(hs, Wp[k], accs[s]);                                 \
    }                                                                        \
} while (0)

#define CONSUME(S) do {                                                      \
    float Ma, Mb, Sa, Sb;                                                    \
    up2(accm[(S)], Ma, Mb);                                                  \
    up2(accs[(S)], Sa, Sb);                                                  \
    const float A2 = Ma * Ma, B2 = Mb * Mb;                                  \
    const float dd = 0.5f * (A2 - B2);   /* mu1*mu2            */            \
    const float pq = 0.5f * (A2 + B2);   /* mu1^2 + mu2^2      */            \
    const float q1 = 0.5f * (Sa - Sb);   /* 2*E[pt]            */            \
    const float q2 = 0.5f * (Sa + Sb);   /* E[p^2] + E[t^2]    */            \
    const float num = (dd + C1f) * (q1 - dd + C2f);                          \
    const float den = (pq + C1f) * (q2 - pq + C2f);                          \
    lsum += __fdividef(num, den);                                            \
    accm[(S)] = 0ull; accs[(S)] = 0ull;                                      \
} while (0)

__global__ __launch_bounds__(128) void ssim_main_kernel(
    const float* __restrict__ pred, const float* __restrict__ target)
{
    // Gaussian(sigma=1.5), window 11, normalized.
    constexpr float Wc[11] = {
        0.00102838f, 0.00759876f, 0.03600077f, 0.10936070f, 0.21300553f,
        0.26601212f,
        0.21300553f, 0.10936070f, 0.03600077f, 0.00759876f, 0.00102838f
    };
    constexpr float C1f = 0.0001f;   // 0.01^2
    constexpr float C2f = 0.0009f;   // 0.03^2

    const int lane  = threadIdx.x & 31;
    const int warp  = threadIdx.x >> 5;
    const int plane = blockIdx.x >> 4;         // 0..47
    const int x0    = (blockIdx.x & 15) << 5;  // column tile * 32

    const float* __restrict__ P = pred   + (size_t)plane * (512 * 512);
    const float* __restrict__ T = target + (size_t)plane * (512 * 512);

    const int y0 = warp << 7;        // first output row for this warp (128 rows)
    const int c0 = x0 - 5 + lane;    // staged columns [x0-5, x0+37)
    const int c1 = x0 + 27 + lane;   // extra 10 columns (lanes 0..9)

    __shared__ unsigned long long ab[4][2 * 48];  // per-warp double-buffered row
    unsigned long long* abw = ab[warp];

    unsigned long long Wp[11];
#pragma unroll
    for (int i = 0; i < 11; ++i) Wp[i] = pk2(Wc[i], Wc[i]);

    unsigned long long accm[11], accs[11];
#pragma unroll
    for (int s = 0; s < 11; ++s) { accm[s] = 0ull; accs[s] = 0ull; }

    unsigned long long hm, hs;
    float lsum = 0.0f;

    // ---- Prologue: input rows j = 0..10, fully compile-time (guards free) ----
#pragma unroll
    for (int j = 0; j <= 10; ++j) {
        const int yy = y0 - 5 + j;
        if (yy >= 0) {                 // top halo (yy < 512 always here)
            STAGE(j & 1, yy);
            HPASS(j & 1);
            VPASS(j, j);               // only taps k <= j exist yet
        }
        if (j == 10) CONSUME(0);       // output row 0 complete
    }

    // ---- Steady: input rows j = 11..137, no tap guards needed ----
    // (upper-guard elimination is safe: slot aliases are >= 11 rows apart,
    //  and consumed slots are reset before reuse)
    for (int jb = 11; jb < 138; jb += 11) {
#pragma unroll
        for (int u = 0; u < 11; ++u) {
            const int j = jb + u;
            if (j < 138) {
                const int yy = y0 - 5 + j;
                const int buf = j & 1;
                if (yy < 512) {        // bottom halo (zero-pad => skip)
                    STAGE(buf, yy);
                    HPASS(buf);
                    VPASS(u, 10);
                }
                CONSUME((u + 1) % 11); // output row j-10 complete
            }
        }
    }

    // ---- Reduce: warp shfl -> CTA smem -> per-CTA partial (no atomics) ----
#pragma unroll
    for (int off = 16; off > 0; off >>= 1)
        lsum += __shfl_xor_sync(0xffffffffu, lsum, off);

    __shared__ float wsum[4];
    if (lane == 0) wsum[warp] = lsum;
    __syncthreads();
    if (threadIdx.x == 0) {
        g_partials[blockIdx.x] =
            (double)wsum[0] + (double)wsum[1] + (double)wsum[2] + (double)wsum[3];
    }
}

__global__ void ssim_final_kernel(float* __restrict__ out) {
    __shared__ double sm[128];
    double s = 0.0;
    for (int i = threadIdx.x; i < 768; i += 128) s += g_partials[i];
    sm[threadIdx.x] = s;
    __syncthreads();
    for (int off = 64; off > 0; off >>= 1) {
        if (threadIdx.x < off) sm[threadIdx.x] += sm[threadIdx.x + off];
        __syncthreads();
    }
    if (threadIdx.x == 0)
        out[0] = (float)(1.0 - sm[0] * (1.0 / 12582912.0));
}

extern "C" void kernel_launch(void* const* d_in, const int* in_sizes, int n_in,
                              void* d_out, int out_size) {
    const float* pred   = (const float*)d_in[0];
    const float* target = (const float*)d_in[1];
    float* out = (float*)d_out;
    (void)in_sizes; (void)n_in; (void)out_size;

    ssim_main_kernel<<<768, 128>>>(pred, target);
    ssim_final_kernel<<<1, 128>>>(out);
}